// round 15
// baseline (speedup 1.0000x reference)
#include <cuda_runtime.h>

// Inverse 3D Haar synthesis (final — compulsory-DRAM-traffic bound):
//   in  : [B=2, 8*16, T=8, H=128, W=128] fp32 (8 subbands of 16 channels)
//   out : [B=2, 16, 16, 256, 256] fp32
// out[b,g,2t+pt,2h+ph,2w+pw] = (1/8) * sum_s (-1)^(bt*pt+bh*ph+bw*pw) * x[b, s*16+g, t, h, w]
// with s = 4*bt + 2*bh + bw.
//
// One thread owns 2 consecutive input w: 8x LDG.64 fully-coalesced subband
// streams. Each (pt,ph) output row is 4 contiguous floats -> one STG.128 at
// lane-stride 16B (fully dense 512B/warp per instruction).
//
// Measured floor across 14 variants: steady-state replay period =
// ~255MB compulsory DRAM traffic / ~5.9TB/s sustained mixed r/w bandwidth
// ~= 43.5us, invariant under store path (STG/TMA), transaction size
// (64b..8KB), all L2 policy hints (silicon no-ops), occupancy, and wave
// structure. This configuration produced the best measured wall (43.488us).

__device__ __forceinline__ float2 f2add(float2 a, float2 b) {
    return make_float2(a.x + b.x, a.y + b.y);
}
__device__ __forceinline__ float2 f2sub(float2 a, float2 b) {
    return make_float2(a.x - b.x, a.y - b.y);
}

__global__ __launch_bounds__(256) void ihaar3d_kernel(const float* __restrict__ x,
                                                      float* __restrict__ out) {
    // Linear decode: [b(1)][g(4)][t(3)][h(7)][w2(6)] bits -> 2^21 threads.
    const int idx = blockIdx.x * blockDim.x + threadIdx.x;
    const int w2 = idx & 63;          // which pair of input w
    const int h  = (idx >> 6) & 127;
    const int t  = (idx >> 13) & 7;
    const int g  = (idx >> 16) & 15;
    const int b  = (idx >> 20) & 1;

    const int w0 = w2 << 1;  // input w of first element

    // input: [B, 128, 8, 128, 128]; subband stride = 16 channels. Offsets fit int32.
    const int SUB = 16 * 8 * 128 * 128;  // 2,097,152
    const int base = (((b * 128 + g) * 8 + t) * 128 + h) * 128 + w0;

    float2 v0 = *reinterpret_cast<const float2*>(x + base + 0 * SUB);  // lll
    float2 v1 = *reinterpret_cast<const float2*>(x + base + 1 * SUB);  // llh
    float2 v2 = *reinterpret_cast<const float2*>(x + base + 2 * SUB);  // lhl
    float2 v3 = *reinterpret_cast<const float2*>(x + base + 3 * SUB);  // lhh
    float2 v4 = *reinterpret_cast<const float2*>(x + base + 4 * SUB);  // hll
    float2 v5 = *reinterpret_cast<const float2*>(x + base + 5 * SUB);  // hlh
    float2 v6 = *reinterpret_cast<const float2*>(x + base + 6 * SUB);  // hhl
    float2 v7 = *reinterpret_cast<const float2*>(x + base + 7 * SUB);  // hhh

    // Stage 1: W butterfly (bit0): e = even W parity, o = odd W parity.
    float2 ll_e = f2add(v0, v1), ll_o = f2sub(v0, v1);
    float2 lh_e = f2add(v2, v3), lh_o = f2sub(v2, v3);
    float2 hl_e = f2add(v4, v5), hl_o = f2sub(v4, v5);
    float2 hh_e = f2add(v6, v7), hh_o = f2sub(v6, v7);

    // Stage 2: H butterfly (bit1): index = ph.
    float2 l0e = f2add(ll_e, lh_e), l1e = f2sub(ll_e, lh_e);
    float2 l0o = f2add(ll_o, lh_o), l1o = f2sub(ll_o, lh_o);
    float2 h0e = f2add(hl_e, hh_e), h1e = f2sub(hl_e, hh_e);
    float2 h0o = f2add(hl_o, hh_o), h1o = f2sub(hl_o, hh_o);

    // Stage 3: T butterfly (bit2) + scale + interleaved store.
    // out: [2, 16, 16, 256, 256]; offsets fit int32.
    const float k = 0.125f;
    const int obase = (((b * 16 + g) * 16 + 2 * t) * 256 + 2 * h) * 256 + 2 * w0;
    const int PT = 256 * 256;
    const int PH = 256;

    float2 le[2] = {l0e, l1e}, lo[2] = {l0o, l1o};
    float2 he[2] = {h0e, h1e}, ho[2] = {h0o, h1o};

#pragma unroll
    for (int pt = 0; pt < 2; ++pt) {
#pragma unroll
        for (int ph = 0; ph < 2; ++ph) {
            float2 e = pt == 0 ? f2add(le[ph], he[ph]) : f2sub(le[ph], he[ph]);
            float2 o = pt == 0 ? f2add(lo[ph], ho[ph]) : f2sub(lo[ph], ho[ph]);
            *reinterpret_cast<float4*>(out + obase + pt * PT + ph * PH) =
                make_float4(e.x * k, o.x * k, e.y * k, o.y * k);
        }
    }
}

extern "C" void kernel_launch(void* const* d_in, const int* in_sizes, int n_in,
                              void* d_out, int out_size) {
    const float* x = (const float*)d_in[0];
    float* out = (float*)d_out;
    // total threads = 2*16*8*128*64 = 2,097,152
    ihaar3d_kernel<<<8192, 256>>>(x, out);
}

// round 16
// speedup vs baseline: 1.0029x; 1.0029x over previous
#include <cuda_runtime.h>

// Inverse 3D Haar synthesis (final — compulsory-DRAM-traffic bound):
//   in  : [B=2, 8*16, T=8, H=128, W=128] fp32 (8 subbands of 16 channels)
//   out : [B=2, 16, 16, 256, 256] fp32
// out[b,g,2t+pt,2h+ph,2w+pw] = (1/8) * sum_s (-1)^(bt*pt+bh*ph+bw*pw) * x[b, s*16+g, t, h, w]
// with s = 4*bt + 2*bh + bw.
//
// One thread owns 2 consecutive input w: 8x LDG.64 fully-coalesced subband
// streams (MLP=8). Each (pt,ph) output row is 4 contiguous floats -> one
// STG.128 at lane-stride 16B (fully dense 512B/warp per instruction).
//
// 15-round conclusion: steady-state replay period = ~255MB compulsory DRAM
// traffic / ~5.9-6.1TB/s sustained mixed r/w bandwidth ~= 43.5us +- 1us
// run-to-run noise. Invariant under store path (STG/TMA/v8), transaction
// size (64b..8KB bursts), all L2 policy hints (wt/cs/evict_* — silicon
// no-ops on this traffic), occupancy (21-84%), wave structure (1-7 waves),
// and MLP (8-16). Best measured wall: 43.488us with this configuration.

__device__ __forceinline__ float2 f2add(float2 a, float2 b) {
    return make_float2(a.x + b.x, a.y + b.y);
}
__device__ __forceinline__ float2 f2sub(float2 a, float2 b) {
    return make_float2(a.x - b.x, a.y - b.y);
}

__global__ __launch_bounds__(256) void ihaar3d_kernel(const float* __restrict__ x,
                                                      float* __restrict__ out) {
    // Linear decode: [b(1)][g(4)][t(3)][h(7)][w2(6)] bits -> 2^21 threads.
    const int idx = blockIdx.x * blockDim.x + threadIdx.x;
    const int w2 = idx & 63;          // which pair of input w
    const int h  = (idx >> 6) & 127;
    const int t  = (idx >> 13) & 7;
    const int g  = (idx >> 16) & 15;
    const int b  = (idx >> 20) & 1;

    const int w0 = w2 << 1;  // input w of first element

    // input: [B, 128, 8, 128, 128]; subband stride = 16 channels. Offsets fit int32.
    const int SUB = 16 * 8 * 128 * 128;  // 2,097,152
    const int base = (((b * 128 + g) * 8 + t) * 128 + h) * 128 + w0;

    float2 v0 = *reinterpret_cast<const float2*>(x + base + 0 * SUB);  // lll
    float2 v1 = *reinterpret_cast<const float2*>(x + base + 1 * SUB);  // llh
    float2 v2 = *reinterpret_cast<const float2*>(x + base + 2 * SUB);  // lhl
    float2 v3 = *reinterpret_cast<const float2*>(x + base + 3 * SUB);  // lhh
    float2 v4 = *reinterpret_cast<const float2*>(x + base + 4 * SUB);  // hll
    float2 v5 = *reinterpret_cast<const float2*>(x + base + 5 * SUB);  // hlh
    float2 v6 = *reinterpret_cast<const float2*>(x + base + 6 * SUB);  // hhl
    float2 v7 = *reinterpret_cast<const float2*>(x + base + 7 * SUB);  // hhh

    // Stage 1: W butterfly (bit0): e = even W parity, o = odd W parity.
    float2 ll_e = f2add(v0, v1), ll_o = f2sub(v0, v1);
    float2 lh_e = f2add(v2, v3), lh_o = f2sub(v2, v3);
    float2 hl_e = f2add(v4, v5), hl_o = f2sub(v4, v5);
    float2 hh_e = f2add(v6, v7), hh_o = f2sub(v6, v7);

    // Stage 2: H butterfly (bit1): index = ph.
    float2 l0e = f2add(ll_e, lh_e), l1e = f2sub(ll_e, lh_e);
    float2 l0o = f2add(ll_o, lh_o), l1o = f2sub(ll_o, lh_o);
    float2 h0e = f2add(hl_e, hh_e), h1e = f2sub(hl_e, hh_e);
    float2 h0o = f2add(hl_o, hh_o), h1o = f2sub(hl_o, hh_o);

    // Stage 3: T butterfly (bit2) + scale + interleaved store.
    // out: [2, 16, 16, 256, 256]; offsets fit int32.
    const float k = 0.125f;
    const int obase = (((b * 16 + g) * 16 + 2 * t) * 256 + 2 * h) * 256 + 2 * w0;
    const int PT = 256 * 256;
    const int PH = 256;

    float2 le[2] = {l0e, l1e}, lo[2] = {l0o, l1o};
    float2 he[2] = {h0e, h1e}, ho[2] = {h0o, h1o};

#pragma unroll
    for (int pt = 0; pt < 2; ++pt) {
#pragma unroll
        for (int ph = 0; ph < 2; ++ph) {
            float2 e = pt == 0 ? f2add(le[ph], he[ph]) : f2sub(le[ph], he[ph]);
            float2 o = pt == 0 ? f2add(lo[ph], ho[ph]) : f2sub(lo[ph], ho[ph]);
            *reinterpret_cast<float4*>(out + obase + pt * PT + ph * PH) =
                make_float4(e.x * k, o.x * k, e.y * k, o.y * k);
        }
    }
}

extern "C" void kernel_launch(void* const* d_in, const int* in_sizes, int n_in,
                              void* d_out, int out_size) {
    const float* x = (const float*)d_in[0];
    float* out = (float*)d_out;
    // total threads = 2*16*8*128*64 = 2,097,152
    ihaar3d_kernel<<<8192, 256>>>(x, out);
}